// round 1
// baseline (speedup 1.0000x reference)
#include <cuda_runtime.h>
#include <cstdint>

// Problem constants (fixed by the reference)
#define DIN  4096
#define DOUT 4096
#define MTOT 8192           // B*S = 4*2048
static __device__ __constant__ float kScaling = 2.0f;  // 32.0 / 16

// ---------------------------------------------------------------------------
// Device-global scratch (allocation-free per harness rules)
// ---------------------------------------------------------------------------
__device__ float g_Weff[(size_t)DOUT * DIN];   // 64 MB folded weight
__device__ int   g_flags[2];                   // [0]=not-float01, [1]=not-int01
__device__ int   g_mode;                       // 0=f32 mask, 1=int32 mask, 2=uint8 mask

// ---------------------------------------------------------------------------
// Mask dtype detection: scan first 16 MB (= 4M words). 16 MB is the minimum
// buffer size across uint8/int32/float32 encodings of the 16.7M-element mask,
// so this never reads out of bounds.
//   float32 mask: every word is 0x00000000 or 0x3F800000
//   int32   mask: every word is 0 or 1
//   uint8   mask: words contain byte patterns violating both of the above
// ---------------------------------------------------------------------------
__global__ void reset_flags_kernel() {
    g_flags[0] = 0;
    g_flags[1] = 0;
}

__global__ void detect_mask_kernel(const unsigned int* __restrict__ w, int nwords) {
    int notF = 0, notI = 0;
    int stride = gridDim.x * blockDim.x;
    for (int i = blockIdx.x * blockDim.x + threadIdx.x; i < nwords; i += stride) {
        unsigned int v = w[i];
        if (v != 0u && v != 0x3F800000u) notF = 1;
        if (v > 1u)                       notI = 1;
    }
    notF = __any_sync(0xFFFFFFFFu, notF);
    notI = __any_sync(0xFFFFFFFFu, notI);
    if ((threadIdx.x & 31) == 0) {
        if (notF) atomicOr(&g_flags[0], 1);
        if (notI) atomicOr(&g_flags[1], 1);
    }
}

__global__ void resolve_mode_kernel() {
    g_mode = (g_flags[0] == 0) ? 0 : ((g_flags[1] == 0) ? 1 : 2);
}

// ---------------------------------------------------------------------------
// Fold: W_eff[o][d] = W[o][d] + delta[o][d]*mask[o][d]
//                   + kScaling * sum_r lora_B[o][r] * lora_A[r][d]
// One block per output row o; 256 threads, float4-vectorized over d.
// ---------------------------------------------------------------------------
__global__ void fold_kernel(const float* __restrict__ W,
                            const float* __restrict__ lora_A,
                            const float* __restrict__ lora_B,
                            const float* __restrict__ delta,
                            const void*  __restrict__ maskp) {
    int o = blockIdx.x;
    __shared__ float br[16];
    if (threadIdx.x < 16) br[threadIdx.x] = lora_B[o * 16 + threadIdx.x] * kScaling;
    __syncthreads();

    const int mode = g_mode;
    const size_t rowoff = (size_t)o * DIN;

    for (int d = threadIdx.x * 4; d < DIN; d += blockDim.x * 4) {
        float4 w4 = *(const float4*)(W + rowoff + d);
        float4 dl = *(const float4*)(delta + rowoff + d);

        float m0, m1, m2, m3;
        if (mode == 0) {
            float4 mf = *(const float4*)((const float*)maskp + rowoff + d);
            m0 = mf.x; m1 = mf.y; m2 = mf.z; m3 = mf.w;
        } else if (mode == 1) {
            int4 mi = *(const int4*)((const int*)maskp + rowoff + d);
            m0 = mi.x ? 1.0f : 0.0f; m1 = mi.y ? 1.0f : 0.0f;
            m2 = mi.z ? 1.0f : 0.0f; m3 = mi.w ? 1.0f : 0.0f;
        } else {
            uchar4 mu = *(const uchar4*)((const unsigned char*)maskp + rowoff + d);
            m0 = mu.x ? 1.0f : 0.0f; m1 = mu.y ? 1.0f : 0.0f;
            m2 = mu.z ? 1.0f : 0.0f; m3 = mu.w ? 1.0f : 0.0f;
        }

        float l0 = 0.f, l1 = 0.f, l2 = 0.f, l3 = 0.f;
#pragma unroll
        for (int r = 0; r < 16; r++) {
            float4 a4 = *(const float4*)(lora_A + (size_t)r * DIN + d);
            float s = br[r];
            l0 = fmaf(s, a4.x, l0);
            l1 = fmaf(s, a4.y, l1);
            l2 = fmaf(s, a4.z, l2);
            l3 = fmaf(s, a4.w, l3);
        }

        float4 out;
        out.x = w4.x + dl.x * m0 + l0;
        out.y = w4.y + dl.y * m1 + l1;
        out.z = w4.z + dl.z * m2 + l2;
        out.w = w4.w + dl.w * m3 + l3;
        *(float4*)(g_Weff + rowoff + d) = out;
    }
}

// ---------------------------------------------------------------------------
// SGEMM: out[m][n] = sum_k X[m][k] * Weff[n][k] + bias[n]
// Block tile 128x128, K-tile 8, 256 threads, 8x8 per-thread micro-tile.
// As padded to 132 floats/row to kill STS bank conflicts on transpose-store.
// ---------------------------------------------------------------------------
#define BM 128
#define BN 128
#define BK 8
#define APAD 132

__global__ __launch_bounds__(256, 2)
void sgemm_kernel(const float* __restrict__ X,
                  const float* __restrict__ bias,
                  float* __restrict__ out) {
    __shared__ float As[BK][APAD];
    __shared__ float Bs[BK][APAD];

    const int bm = blockIdx.y * BM;
    const int bn = blockIdx.x * BN;
    const int tid = threadIdx.x;

    // global-load mapping: each thread loads one float4 per tile per k-step
    const int loadRow = tid >> 1;           // 0..127
    const int loadCol = (tid & 1) * 4;      // 0 or 4
    const float* xPtr = X      + (size_t)(bm + loadRow) * DIN + loadCol;
    const float* wPtr = g_Weff + (size_t)(bn + loadRow) * DIN + loadCol;

    const int tx = tid & 15;                // n-direction
    const int ty = tid >> 4;                // m-direction

    float acc[8][8];
#pragma unroll
    for (int i = 0; i < 8; i++)
#pragma unroll
        for (int j = 0; j < 8; j++) acc[i][j] = 0.0f;

    for (int k0 = 0; k0 < DIN; k0 += BK) {
        float4 xa = *(const float4*)(xPtr + k0);
        float4 wa = *(const float4*)(wPtr + k0);

        __syncthreads();   // previous compute done before overwriting smem
        As[loadCol + 0][loadRow] = xa.x;
        As[loadCol + 1][loadRow] = xa.y;
        As[loadCol + 2][loadRow] = xa.z;
        As[loadCol + 3][loadRow] = xa.w;
        Bs[loadCol + 0][loadRow] = wa.x;
        Bs[loadCol + 1][loadRow] = wa.y;
        Bs[loadCol + 2][loadRow] = wa.z;
        Bs[loadCol + 3][loadRow] = wa.w;
        __syncthreads();

#pragma unroll
        for (int kk = 0; kk < BK; kk++) {
            float4 a0 = *(const float4*)&As[kk][ty * 8];
            float4 a1 = *(const float4*)&As[kk][ty * 8 + 4];
            float4 b0 = *(const float4*)&Bs[kk][tx * 8];
            float4 b1 = *(const float4*)&Bs[kk][tx * 8 + 4];
            float a[8] = {a0.x, a0.y, a0.z, a0.w, a1.x, a1.y, a1.z, a1.w};
            float b[8] = {b0.x, b0.y, b0.z, b0.w, b1.x, b1.y, b1.z, b1.w};
#pragma unroll
            for (int i = 0; i < 8; i++)
#pragma unroll
                for (int j = 0; j < 8; j++)
                    acc[i][j] = fmaf(a[i], b[j], acc[i][j]);
        }
    }

    // epilogue: add bias, vectorized stores
    float bv[8];
#pragma unroll
    for (int j = 0; j < 8; j++) bv[j] = bias[bn + tx * 8 + j];

#pragma unroll
    for (int i = 0; i < 8; i++) {
        int m = bm + ty * 8 + i;
        float* op = out + (size_t)m * DOUT + bn + tx * 8;
        float4 v0, v1;
        v0.x = acc[i][0] + bv[0]; v0.y = acc[i][1] + bv[1];
        v0.z = acc[i][2] + bv[2]; v0.w = acc[i][3] + bv[3];
        v1.x = acc[i][4] + bv[4]; v1.y = acc[i][5] + bv[5];
        v1.z = acc[i][6] + bv[6]; v1.w = acc[i][7] + bv[7];
        *(float4*)(op)     = v0;
        *(float4*)(op + 4) = v1;
    }
}

// ---------------------------------------------------------------------------
// Launch: detect mask dtype -> fold weights -> single GEMM
// All launches on the default stream (sequential), graph-capturable,
// no allocations, deterministic.
// ---------------------------------------------------------------------------
extern "C" void kernel_launch(void* const* d_in, const int* in_sizes, int n_in,
                              void* d_out, int out_size) {
    const float* x      = (const float*)d_in[0];
    const float* W      = (const float*)d_in[1];
    const float* b      = (const float*)d_in[2];
    const float* lora_A = (const float*)d_in[3];
    const float* lora_B = (const float*)d_in[4];
    const float* delta  = (const float*)d_in[5];
    const void*  mask   = d_in[6];

    reset_flags_kernel<<<1, 1>>>();
    // 16 MB = 4M words: safe lower bound on mask buffer size for all dtypes
    detect_mask_kernel<<<256, 256>>>((const unsigned int*)mask, 4 * 1024 * 1024);
    resolve_mode_kernel<<<1, 1>>>();

    fold_kernel<<<DOUT, 256>>>(W, lora_A, lora_B, delta, mask);

    dim3 grid(DOUT / BN, MTOT / BM);   // (32, 64)
    sgemm_kernel<<<grid, 256>>>(x, b, (float*)d_out);
}

// round 3
// speedup vs baseline: 3.3341x; 3.3341x over previous
#include <cuda_runtime.h>
#include <cuda_bf16.h>
#include <cstdint>

// ---------------------------------------------------------------------------
// Problem constants
// ---------------------------------------------------------------------------
#define DIN   4096
#define DOUT  4096
#define MTOT  8192
#define NSEG  3
#define BK    64                          // bf16 elems per k-chunk (128 B/row)
#define NCHUNK ((DIN / BK) * NSEG)        // 192
#define BM    128
#define BN    128
#define NSTAGE 3
#define STAGE_BYTES 32768                 // A 16KB + B 16KB
#define SMEM_TOTAL (NSTAGE * STAGE_BYTES) // 96 KB
static __device__ __constant__ float kScaling = 2.0f;   // 32 / rank(16)

// ---------------------------------------------------------------------------
// Device-global scratch (allocation-free rules)
// ---------------------------------------------------------------------------
__device__ __nv_bfloat16 g_Xhi[(size_t)MTOT * DIN];
__device__ __nv_bfloat16 g_Xlo[(size_t)MTOT * DIN];
__device__ __nv_bfloat16 g_Whi[(size_t)DOUT * DIN];
__device__ __nv_bfloat16 g_Wlo[(size_t)DOUT * DIN];
__device__ int g_flags[2];
__device__ int g_mode;

// ---------------------------------------------------------------------------
// Helpers (all baseline-PTX, compile at compute_103)
// ---------------------------------------------------------------------------
__device__ __forceinline__ uint32_t smem_u32(const void* p) {
    uint32_t a;
    asm("{ .reg .u64 t; cvta.to.shared.u64 t, %1; cvt.u32.u64 %0, t; }" : "=r"(a) : "l"(p));
    return a;
}
__device__ __forceinline__ void cp_async16(uint32_t dst, const void* src) {
    asm volatile("cp.async.cg.shared.global [%0], [%1], 16;"
                 :: "r"(dst), "l"(__cvta_generic_to_global(src)));
}
#define CP_COMMIT() asm volatile("cp.async.commit_group;" ::: "memory")
#define CP_WAIT(n)  asm volatile("cp.async.wait_group %0;" :: "n"(n) : "memory")

__device__ __forceinline__ uint32_t swz(uint32_t o) { return o ^ ((o >> 3) & 0x70); }

__device__ __forceinline__ void ldsm_x4(uint32_t* r, uint32_t addr) {
    asm volatile("ldmatrix.sync.aligned.m8n8.x4.shared.b16 {%0,%1,%2,%3}, [%4];"
                 : "=r"(r[0]), "=r"(r[1]), "=r"(r[2]), "=r"(r[3]) : "r"(addr));
}
__device__ __forceinline__ void mma_bf16(float* c, const uint32_t* a,
                                         uint32_t b0, uint32_t b1) {
    asm volatile(
        "mma.sync.aligned.m16n8k16.row.col.f32.bf16.bf16.f32 "
        "{%0,%1,%2,%3}, {%4,%5,%6,%7}, {%8,%9}, {%0,%1,%2,%3};"
        : "+f"(c[0]), "+f"(c[1]), "+f"(c[2]), "+f"(c[3])
        : "r"(a[0]), "r"(a[1]), "r"(a[2]), "r"(a[3]), "r"(b0), "r"(b1));
}

__device__ __forceinline__ void split_bf16(float v, uint32_t& hbits, uint32_t& lbits) {
    __nv_bfloat16 h = __float2bfloat16(v);
    __nv_bfloat16 l = __float2bfloat16(v - __bfloat162float(h));
    hbits = (uint32_t)__bfloat16_as_ushort(h);
    lbits = (uint32_t)__bfloat16_as_ushort(l);
}

// ---------------------------------------------------------------------------
// Mask dtype detection (first 16MB scan = safe lower bound for all dtypes)
// ---------------------------------------------------------------------------
__global__ void reset_flags_kernel() { g_flags[0] = 0; g_flags[1] = 0; }

__global__ void detect_mask_kernel(const unsigned int* __restrict__ w, int nwords) {
    int notF = 0, notI = 0;
    int stride = gridDim.x * blockDim.x;
    for (int i = blockIdx.x * blockDim.x + threadIdx.x; i < nwords; i += stride) {
        unsigned int v = w[i];
        if (v != 0u && v != 0x3F800000u) notF = 1;
        if (v > 1u)                       notI = 1;
    }
    notF = __any_sync(0xFFFFFFFFu, notF);
    notI = __any_sync(0xFFFFFFFFu, notI);
    if ((threadIdx.x & 31) == 0) {
        if (notF) atomicOr(&g_flags[0], 1);
        if (notI) atomicOr(&g_flags[1], 1);
    }
}
__global__ void resolve_mode_kernel() {
    g_mode = (g_flags[0] == 0) ? 0 : ((g_flags[1] == 0) ? 1 : 2);
}

// ---------------------------------------------------------------------------
// Fold W_eff = W + delta*mask + 2*(B@A) → bf16 hi/lo
// ---------------------------------------------------------------------------
__global__ void fold_kernel(const float* __restrict__ W,
                            const float* __restrict__ lora_A,
                            const float* __restrict__ lora_B,
                            const float* __restrict__ delta,
                            const void*  __restrict__ maskp) {
    int o = blockIdx.x;
    __shared__ float br[16];
    if (threadIdx.x < 16) br[threadIdx.x] = lora_B[o * 16 + threadIdx.x] * kScaling;
    __syncthreads();

    const int mode = g_mode;
    const size_t rowoff = (size_t)o * DIN;

    for (int d = threadIdx.x * 4; d < DIN; d += blockDim.x * 4) {
        float4 w4 = *(const float4*)(W + rowoff + d);
        float4 dl = *(const float4*)(delta + rowoff + d);

        float m0, m1, m2, m3;
        if (mode == 0) {
            float4 mf = *(const float4*)((const float*)maskp + rowoff + d);
            m0 = mf.x; m1 = mf.y; m2 = mf.z; m3 = mf.w;
        } else if (mode == 1) {
            int4 mi = *(const int4*)((const int*)maskp + rowoff + d);
            m0 = mi.x ? 1.f : 0.f; m1 = mi.y ? 1.f : 0.f;
            m2 = mi.z ? 1.f : 0.f; m3 = mi.w ? 1.f : 0.f;
        } else {
            uchar4 mu = *(const uchar4*)((const unsigned char*)maskp + rowoff + d);
            m0 = mu.x ? 1.f : 0.f; m1 = mu.y ? 1.f : 0.f;
            m2 = mu.z ? 1.f : 0.f; m3 = mu.w ? 1.f : 0.f;
        }

        float l0 = 0.f, l1 = 0.f, l2 = 0.f, l3 = 0.f;
#pragma unroll
        for (int r = 0; r < 16; r++) {
            float4 a4 = *(const float4*)(lora_A + (size_t)r * DIN + d);
            float s = br[r];
            l0 = fmaf(s, a4.x, l0); l1 = fmaf(s, a4.y, l1);
            l2 = fmaf(s, a4.z, l2); l3 = fmaf(s, a4.w, l3);
        }

        float v0 = w4.x + dl.x * m0 + l0;
        float v1 = w4.y + dl.y * m1 + l1;
        float v2 = w4.z + dl.z * m2 + l2;
        float v3 = w4.w + dl.w * m3 + l3;

        uint32_t h0,h1,h2,h3,q0,q1,q2,q3;
        split_bf16(v0,h0,q0); split_bf16(v1,h1,q1);
        split_bf16(v2,h2,q2); split_bf16(v3,h3,q3);
        uint2 H = make_uint2(h0 | (h1<<16), h2 | (h3<<16));
        uint2 L = make_uint2(q0 | (q1<<16), q2 | (q3<<16));
        *(uint2*)((char*)g_Whi + (rowoff + d) * 2) = H;
        *(uint2*)((char*)g_Wlo + (rowoff + d) * 2) = L;
    }
}

// ---------------------------------------------------------------------------
// X → bf16 hi/lo split
// ---------------------------------------------------------------------------
__global__ void convert_x_kernel(const float* __restrict__ x) {
    size_t base = ((size_t)blockIdx.x * blockDim.x + threadIdx.x) * 4;
    float4 v = *(const float4*)(x + base);
    uint32_t h0,h1,h2,h3,q0,q1,q2,q3;
    split_bf16(v.x,h0,q0); split_bf16(v.y,h1,q1);
    split_bf16(v.z,h2,q2); split_bf16(v.w,h3,q3);
    uint2 H = make_uint2(h0 | (h1<<16), h2 | (h3<<16));
    uint2 L = make_uint2(q0 | (q1<<16), q2 | (q3<<16));
    *(uint2*)((char*)g_Xhi + base * 2) = H;
    *(uint2*)((char*)g_Xlo + base * 2) = L;
}

// ---------------------------------------------------------------------------
// HMMA bf16 GEMM: out[128x128 tile] = A'[128,12288]·B'[128,12288]^T + bias
// segments: k∈[0,64): Xhi·Whi ; [64,128): Xlo·Whi ; [128,192): Xhi·Wlo (chunks)
// 8 warps (4m × 2n), warp tile 32x64, mma m16n8k16, 3-stage cp.async pipe.
// ---------------------------------------------------------------------------
__global__ __launch_bounds__(256, 2)
void gemm_kernel(const float* __restrict__ bias, float* __restrict__ out) {
    extern __shared__ __align__(1024) char smem[];
    const uint32_t sbase = smem_u32(smem);
    const int tid = threadIdx.x;
    const int lane = tid & 31;
    const int wid = tid >> 5;
    const int warpM = wid >> 1;           // 0..3
    const int warpN = wid & 1;            // 0..1
    const int bm = blockIdx.x * BM;       // m fastest → W stays L2-resident
    const int bn = blockIdx.y * BN;

    // ---- loader slot mapping: 4 A-slots + 4 B-slots of 16B per thread/chunk
    int rowL[4];  uint32_t dstL[4];  int colL[4];
#pragma unroll
    for (int i = 0; i < 4; i++) {
        int slot = tid + 256 * i;         // 0..1023
        rowL[i] = slot >> 3;              // 0..127
        colL[i] = (slot & 7) * 8;         // bf16 col
        dstL[i] = swz((uint32_t)(rowL[i] * 128 + (slot & 7) * 16));
    }

    // ---- ldmatrix per-lane relative offsets (within a stage tile)
    const int arow  = (lane & 7) + ((lane >> 3) & 1) * 8;
    const int acol  = ((lane >> 4) & 1) * 16;           // byte
    const int brow  = (lane & 7) + ((lane >> 4) & 1) * 8;
    const int bcol  = ((lane >> 3) & 1) * 16;           // byte
    uint32_t relA[2][4], relB[4][4];
#pragma unroll
    for (int mt = 0; mt < 2; mt++)
#pragma unroll
        for (int ks = 0; ks < 4; ks++)
            relA[mt][ks] = swz((uint32_t)((warpM * 32 + mt * 16 + arow) * 128 + ks * 32 + acol));
#pragma unroll
    for (int p = 0; p < 4; p++)
#pragma unroll
        for (int ks = 0; ks < 4; ks++)
            relB[p][ks] = swz((uint32_t)((warpN * 64 + p * 16 + brow) * 128 + ks * 32 + bcol));

    float acc[2][8][4];
#pragma unroll
    for (int mt = 0; mt < 2; mt++)
#pragma unroll
        for (int nt = 0; nt < 8; nt++)
#pragma unroll
            for (int q = 0; q < 4; q++) acc[mt][nt][q] = 0.f;

    auto load_chunk = [&](int c, int stage) {
        const int seg = c >> 6;
        const int kk  = (c & 63) << 6;
        const __nv_bfloat16* As = (seg == 1) ? g_Xlo : g_Xhi;
        const __nv_bfloat16* Bs = (seg == 2) ? g_Wlo : g_Whi;
        const uint32_t aB = sbase + stage * STAGE_BYTES;
        const uint32_t bB = aB + 16384;
#pragma unroll
        for (int i = 0; i < 4; i++)
            cp_async16(aB + dstL[i], As + (size_t)(bm + rowL[i]) * DIN + kk + colL[i]);
#pragma unroll
        for (int i = 0; i < 4; i++)
            cp_async16(bB + dstL[i], Bs + (size_t)(bn + rowL[i]) * DIN + kk + colL[i]);
    };

    // prologue: 2 chunks in flight
    load_chunk(0, 0); CP_COMMIT();
    load_chunk(1, 1); CP_COMMIT();

    for (int c = 0; c < NCHUNK; c++) {
        if (c + 1 < NCHUNK) { CP_WAIT(1); } else { CP_WAIT(0); }
        __syncthreads();
        if (c + 2 < NCHUNK) { load_chunk(c + 2, (c + 2) % NSTAGE); CP_COMMIT(); }

        const uint32_t aB = sbase + (c % NSTAGE) * STAGE_BYTES;
        const uint32_t bB = aB + 16384;
#pragma unroll
        for (int ks = 0; ks < 4; ks++) {
            uint32_t a[2][4];
            ldsm_x4(a[0], aB + relA[0][ks]);
            ldsm_x4(a[1], aB + relA[1][ks]);
            uint32_t b[4][4];
#pragma unroll
            for (int p = 0; p < 4; p++) ldsm_x4(b[p], bB + relB[p][ks]);
#pragma unroll
            for (int mt = 0; mt < 2; mt++)
#pragma unroll
                for (int nt = 0; nt < 8; nt++) {
                    uint32_t b0 = b[nt >> 1][(nt & 1) * 2];
                    uint32_t b1 = b[nt >> 1][(nt & 1) * 2 + 1];
                    mma_bf16(acc[mt][nt], a[mt], b0, b1);
                }
        }
    }

    // ---- epilogue: add bias, store float2 per fragment row
    const int group = lane >> 2;
    const int tig   = lane & 3;
#pragma unroll
    for (int nt = 0; nt < 8; nt++) {
        const int col = bn + warpN * 64 + nt * 8 + tig * 2;
        const float2 bv = *(const float2*)(bias + col);
#pragma unroll
        for (int mt = 0; mt < 2; mt++) {
            const int row0 = bm + warpM * 32 + mt * 16 + group;
            float* p0 = out + (size_t)row0 * DOUT + col;
            float* p1 = out + (size_t)(row0 + 8) * DOUT + col;
            float2 v0 = make_float2(acc[mt][nt][0] + bv.x, acc[mt][nt][1] + bv.y);
            float2 v1 = make_float2(acc[mt][nt][2] + bv.x, acc[mt][nt][3] + bv.y);
            *(float2*)p0 = v0;
            *(float2*)p1 = v1;
        }
    }
}

// ---------------------------------------------------------------------------
// Launch
// ---------------------------------------------------------------------------
extern "C" void kernel_launch(void* const* d_in, const int* in_sizes, int n_in,
                              void* d_out, int out_size) {
    const float* x      = (const float*)d_in[0];
    const float* W      = (const float*)d_in[1];
    const float* b      = (const float*)d_in[2];
    const float* lora_A = (const float*)d_in[3];
    const float* lora_B = (const float*)d_in[4];
    const float* delta  = (const float*)d_in[5];
    const void*  mask   = d_in[6];

    static bool attr_done = false;
    if (!attr_done) {
        cudaFuncSetAttribute(gemm_kernel,
                             cudaFuncAttributeMaxDynamicSharedMemorySize, SMEM_TOTAL);
        attr_done = true;
    }

    reset_flags_kernel<<<1, 1>>>();
    detect_mask_kernel<<<256, 256>>>((const unsigned int*)mask, 4 * 1024 * 1024);
    resolve_mode_kernel<<<1, 1>>>();

    fold_kernel<<<DOUT, 256>>>(W, lora_A, lora_B, delta, mask);
    convert_x_kernel<<<(MTOT * DIN) / 4 / 256, 256>>>(x);

    dim3 grid(MTOT / BM, DOUT / BN);   // (64, 32), m fastest
    gemm_kernel<<<grid, 256, SMEM_TOTAL>>>(b, (float*)d_out);
}